// round 16
// baseline (speedup 1.0000x reference)
#include <cuda_runtime.h>

#define B_TOTAL 2048
#define NPTS    256

typedef unsigned long long ull;

__device__ float g_partial[B_TOTAL];
__device__ int   g_ctr;    // zero-init; last block resets it each run

__device__ __forceinline__ ull pk2(float lo, float hi) {
    ull r; asm("mov.b64 %0, {%1, %2};" : "=l"(r) : "f"(lo), "f"(hi)); return r;
}
// Packed 2-wide fp32 FMA (sm_103a FFMA2; only reachable via PTX f32x2).
__device__ __forceinline__ ull ffma2(ull a, ull b, ull c) {
    ull d; asm("fma.rn.f32x2 %0, %1, %2, %3;" : "=l"(d) : "l"(a), "l"(b), "l"(c));
    return d;
}
__device__ __forceinline__ unsigned lo32(ull v) { return (unsigned)v; }
__device__ __forceinline__ unsigned hi32(ull v) { return (unsigned)(v >> 32); }

// One warp per batch. blockDim = 32, grid = 2048.
// Point k = 8*lane + slot (true input index -> tie-break matches ref).
// Fully register-resident: the "used" set lives in bit31 of km[8]
// (key-material regs). No SMEM state, no __syncwarp in the loop.
// Two targets per iteration; their 5-level SHFL-min butterflies are
// interleaved so the latencies overlap. Rare warp-uniform fallback when
// target j+1's argmin equals target j's.
__global__ __launch_bounds__(32, 1) void match_kernel(const float* __restrict__ inp,
                                                      const float* __restrict__ tgt,
                                                      float* __restrict__ out) {
    const int lane = threadIdx.x;
    const int b = blockIdx.x;

    // Each target j stored as (-2x, -2x, -2y, -2y): one broadcast LDS.128
    // yields both packed f32x2 coefficient registers.
    __shared__ float4 s_tgt4[NPTS];

    // Stage targets; sum |t|^2 from raw values.
    const float4* tg4 = (const float4*)(tgt + (size_t)b * 2 * NPTS);
    float tts = 0.0f;
    #pragma unroll
    for (int i = 0; i < 4; i++) {
        float4 v = tg4[lane + 32 * i];      // targets 2*(lane+32i), +1
        tts += fmaf(v.x, v.x, v.y * v.y) + fmaf(v.z, v.z, v.w * v.w);
        int t0 = 2 * (lane + 32 * i);
        s_tgt4[t0]     = make_float4(-2.0f * v.x, -2.0f * v.x,
                                     -2.0f * v.y, -2.0f * v.y);
        s_tgt4[t0 + 1] = make_float4(-2.0f * v.z, -2.0f * v.z,
                                     -2.0f * v.w, -2.0f * v.w);
    }

    // Own 8 consecutive points (coalesced float4): k = 8*lane + i, kept as
    // packed f32x2 pairs. c = |p|^2 + 64 keeps d positive so uint-min ==
    // float-min AND bit31 of every alive key stays 0.
    ull px2[4], py2[4], c2[4];
    unsigned km[8];   // low byte = global index k; bit31 = dead flag
    const float4* in4 = (const float4*)(inp + (size_t)b * 2 * NPTS);
    #pragma unroll
    for (int p = 0; p < 4; p++) {
        float4 v = in4[4 * lane + p];       // (x2p, y2p, x2p+1, y2p+1)
        px2[p] = pk2(v.x, v.z);
        py2[p] = pk2(v.y, v.w);
        c2[p]  = pk2(fmaf(v.x, v.x, fmaf(v.y, v.y, 64.0f)),
                     fmaf(v.z, v.z, fmaf(v.w, v.w, 64.0f)));
        km[2 * p]     = 8u * (unsigned)lane + 2u * (unsigned)p;
        km[2 * p + 1] = 8u * (unsigned)lane + 2u * (unsigned)p + 1u;
    }

    __syncwarp();   // once: s_tgt4 visible

    float acc = 0.0f;   // uniform across lanes

    #pragma unroll 1
    for (int jj = 0; jj < NPTS / 2; jj++) {
        float4 ta = s_tgt4[2 * jj];         // (-2x,-2x,-2y,-2y) target 2jj
        float4 tb = s_tgt4[2 * jj + 1];     // target 2jj+1
        ull aX = pk2(ta.x, ta.y), aY = pk2(ta.z, ta.w);
        ull bX = pk2(tb.x, tb.y), bY = pk2(tb.z, tb.w);

        // d = |t-p|^2 - |t|^2 + 64 > 0, two points per FFMA2 chain.
        // key = (d_bits & ~0xFF) | km  (one LOP3; dead -> bit31 set -> loses).
        unsigned l0a = ~0u, l0b = ~0u, l1a = ~0u, l1b = ~0u;
        #pragma unroll
        for (int p = 0; p < 4; p++) {
            ull e0 = ffma2(aX, px2[p], ffma2(aY, py2[p], c2[p]));
            ull e1 = ffma2(bX, px2[p], ffma2(bY, py2[p], c2[p]));
            l0a = min(l0a, (lo32(e0) & 0xFFFFFF00u) | km[2 * p]);
            l0b = min(l0b, (hi32(e0) & 0xFFFFFF00u) | km[2 * p + 1]);
            l1a = min(l1a, (lo32(e1) & 0xFFFFFF00u) | km[2 * p]);
            l1b = min(l1b, (hi32(e1) & 0xFFFFFF00u) | km[2 * p + 1]);
        }
        unsigned l0 = min(l0a, l0b);
        unsigned l1 = min(l1a, l1b);

        // Two interleaved 5-level SHFL-min butterflies (latencies overlap).
        #pragma unroll
        for (int off = 16; off; off >>= 1) {
            unsigned o0 = __shfl_xor_sync(0xffffffffu, l0, off);
            unsigned o1 = __shfl_xor_sync(0xffffffffu, l1, off);
            l0 = min(l0, o0);
            l1 = min(l1, o1);
        }
        unsigned kw0 = l0, kw1 = l1;

        // Kill target0's winner in registers (bit31 of km).
        unsigned i0 = kw0 & 0xFFu;
        unsigned t0 = i0 - 8u * (unsigned)lane;   // 0..7 iff mine (else wraps)
        #pragma unroll
        for (int s = 0; s < 8; s++)
            km[s] = (t0 == (unsigned)s) ? (km[s] | 0x80000000u) : km[s];

        // Rare fallback: target1 wanted target0's point. Recompute with the
        // updated km (which now excludes i0). Removing a non-winning element
        // never changes a min, so otherwise kw1 is already correct.
        if (((kw0 ^ kw1) & 0xFFu) == 0u) {
            unsigned r0 = ~0u, r1 = ~0u;
            #pragma unroll
            for (int p = 0; p < 4; p++) {
                ull e1 = ffma2(bX, px2[p], ffma2(bY, py2[p], c2[p]));
                r0 = min(r0, (lo32(e1) & 0xFFFFFF00u) | km[2 * p]);
                r1 = min(r1, (hi32(e1) & 0xFFFFFF00u) | km[2 * p + 1]);
            }
            kw1 = __reduce_min_sync(0xffffffffu, min(r0, r1));
        }

        // Kill target1's winner.
        unsigned i1 = kw1 & 0xFFu;
        unsigned t1 = i1 - 8u * (unsigned)lane;
        #pragma unroll
        for (int s = 0; s < 8; s++)
            km[s] = (t1 == (unsigned)s) ? (km[s] | 0x80000000u) : km[s];

        // Uniform accumulate; index bits are denormal-magnitude noise and
        // 8-bit truncation bias ~2^-16 relative: both << 1e-3 tolerance.
        acc += __uint_as_float(kw0) + __uint_as_float(kw1);
    }

    // Sum of |t|^2 over the batch (warp butterfly, off critical path).
    #pragma unroll
    for (int off = 16; off; off >>= 1)
        tts += __shfl_xor_sync(0xffffffffu, tts, off);

    // se_j = d_j - 64 + |t_j|^2  =>  batch sum = acc + tts - 64*256
    if (lane == 0) g_partial[b] = acc + tts - 64.0f * NPTS;
    __threadfence();

    // Fused deterministic final reduction (last block, fixed order, fp64).
    int last = 0;
    if (lane == 0) last = (atomicAdd(&g_ctr, 1) == B_TOTAL - 1);
    last = __shfl_sync(0xffffffffu, last, 0);
    if (last) {
        __threadfence();
        double s = 0.0;
        #pragma unroll
        for (int i = 0; i < B_TOTAL / 32; i++)
            s += (double)g_partial[lane + 32 * i];
        #pragma unroll
        for (int off = 16; off; off >>= 1)
            s += __shfl_xor_sync(0xffffffffu, s, off);
        if (lane == 0) {
            out[0] = (float)(s / (double)B_TOTAL / (double)(2 * NPTS));
            g_ctr = 0;                  // reset for next graph replay
        }
    }
}

extern "C" void kernel_launch(void* const* d_in, const int* in_sizes, int n_in,
                              void* d_out, int out_size) {
    const float* inp = (const float*)d_in[0];   // "input"
    const float* tgt = (const float*)d_in[1];   // "targets"
    match_kernel<<<B_TOTAL, 32>>>(inp, tgt, (float*)d_out);
}

// round 17
// speedup vs baseline: 1.2761x; 1.2761x over previous
#include <cuda_runtime.h>

#define B_TOTAL 2048
#define NPTS    256

typedef unsigned long long ull;

__device__ float g_partial[B_TOTAL];
__device__ int   g_ctr;    // zero-init; last block resets it each run

__device__ __forceinline__ ull pk2(float lo, float hi) {
    ull r; asm("mov.b64 %0, {%1, %2};" : "=l"(r) : "f"(lo), "f"(hi)); return r;
}
// Packed 2-wide fp32 FMA (sm_103a FFMA2; only reachable via PTX f32x2).
__device__ __forceinline__ ull ffma2(ull a, ull b, ull c) {
    ull d; asm("fma.rn.f32x2 %0, %1, %2, %3;" : "=l"(d) : "l"(a), "l"(b), "l"(c));
    return d;
}
__device__ __forceinline__ unsigned lo32(ull v) { return (unsigned)v; }
__device__ __forceinline__ unsigned hi32(ull v) { return (unsigned)(v >> 32); }

// One warp per batch. blockDim = 32, grid = 2048.
// Point k = 8*lane + slot (true input index -> tie-break matches ref).
// Register-resident "used" set: bit31 of km[8]. No SMEM state / no
// __syncwarp in the loop -> next pair's FFMA2 block is independent of the
// previous kills and overlaps the REDUX latency. Warp reduction via two
// back-to-back hardware REDUX.MIN (NOT a shfl butterfly - R15 showed that
// costs ~2x). Rare warp-uniform fallback when target j+1's argmin equals
// target j's.
__global__ __launch_bounds__(32, 1) void match_kernel(const float* __restrict__ inp,
                                                      const float* __restrict__ tgt,
                                                      float* __restrict__ out) {
    const int lane = threadIdx.x;
    const int b = blockIdx.x;

    // Each target j stored as (-2x, -2x, -2y, -2y): one broadcast LDS.128
    // yields both packed f32x2 coefficient registers.
    __shared__ float4 s_tgt4[NPTS];

    // Stage targets; sum |t|^2 from raw values.
    const float4* tg4 = (const float4*)(tgt + (size_t)b * 2 * NPTS);
    float tts = 0.0f;
    #pragma unroll
    for (int i = 0; i < 4; i++) {
        float4 v = tg4[lane + 32 * i];      // targets 2*(lane+32i), +1
        tts += fmaf(v.x, v.x, v.y * v.y) + fmaf(v.z, v.z, v.w * v.w);
        int t0 = 2 * (lane + 32 * i);
        s_tgt4[t0]     = make_float4(-2.0f * v.x, -2.0f * v.x,
                                     -2.0f * v.y, -2.0f * v.y);
        s_tgt4[t0 + 1] = make_float4(-2.0f * v.z, -2.0f * v.z,
                                     -2.0f * v.w, -2.0f * v.w);
    }

    // Own 8 consecutive points (coalesced float4): k = 8*lane + i, kept as
    // packed f32x2 pairs. c = |p|^2 + 64 keeps d positive so uint-min ==
    // float-min AND bit31 of every alive key stays 0.
    ull px2[4], py2[4], c2[4];
    unsigned km[8];   // low byte = global index k; bit31 = dead flag
    const float4* in4 = (const float4*)(inp + (size_t)b * 2 * NPTS);
    #pragma unroll
    for (int p = 0; p < 4; p++) {
        float4 v = in4[4 * lane + p];       // (x2p, y2p, x2p+1, y2p+1)
        px2[p] = pk2(v.x, v.z);
        py2[p] = pk2(v.y, v.w);
        c2[p]  = pk2(fmaf(v.x, v.x, fmaf(v.y, v.y, 64.0f)),
                     fmaf(v.z, v.z, fmaf(v.w, v.w, 64.0f)));
        km[2 * p]     = 8u * (unsigned)lane + 2u * (unsigned)p;
        km[2 * p + 1] = 8u * (unsigned)lane + 2u * (unsigned)p + 1u;
    }

    __syncwarp();   // once: s_tgt4 visible

    float acc = 0.0f;   // uniform across lanes

    #pragma unroll 2
    for (int jj = 0; jj < NPTS / 2; jj++) {
        float4 ta = s_tgt4[2 * jj];         // (-2x,-2x,-2y,-2y) target 2jj
        float4 tb = s_tgt4[2 * jj + 1];     // target 2jj+1
        ull aX = pk2(ta.x, ta.y), aY = pk2(ta.z, ta.w);
        ull bX = pk2(tb.x, tb.y), bY = pk2(tb.z, tb.w);

        // d = |t-p|^2 - |t|^2 + 64 > 0, two points per FFMA2 chain.
        // key = (d_bits & ~0xFF) | km  (one LOP3; dead -> bit31 set -> loses).
        unsigned l0a = ~0u, l0b = ~0u, l1a = ~0u, l1b = ~0u;
        #pragma unroll
        for (int p = 0; p < 4; p++) {
            ull e0 = ffma2(aX, px2[p], ffma2(aY, py2[p], c2[p]));
            ull e1 = ffma2(bX, px2[p], ffma2(bY, py2[p], c2[p]));
            l0a = min(l0a, (lo32(e0) & 0xFFFFFF00u) | km[2 * p]);
            l0b = min(l0b, (hi32(e0) & 0xFFFFFF00u) | km[2 * p + 1]);
            l1a = min(l1a, (lo32(e1) & 0xFFFFFF00u) | km[2 * p]);
            l1b = min(l1b, (hi32(e1) & 0xFFFFFF00u) | km[2 * p + 1]);
        }
        // Two independent hardware warp-mins, issued back-to-back.
        unsigned kw0 = __reduce_min_sync(0xffffffffu, min(l0a, l0b));
        unsigned kw1 = __reduce_min_sync(0xffffffffu, min(l1a, l1b));

        // Kill target0's winner in registers (bit31 of km).
        unsigned i0 = kw0 & 0xFFu;
        unsigned t0 = i0 - 8u * (unsigned)lane;   // 0..7 iff mine (else wraps)
        #pragma unroll
        for (int s = 0; s < 8; s++)
            km[s] = (t0 == (unsigned)s) ? (km[s] | 0x80000000u) : km[s];

        // Rare fallback: target1 wanted target0's point. Recompute with the
        // updated km (which now excludes i0). Removing a non-winning element
        // never changes a min, so otherwise kw1 is already correct.
        if (((kw0 ^ kw1) & 0xFFu) == 0u) {
            unsigned r0 = ~0u, r1 = ~0u;
            #pragma unroll
            for (int p = 0; p < 4; p++) {
                ull e1 = ffma2(bX, px2[p], ffma2(bY, py2[p], c2[p]));
                r0 = min(r0, (lo32(e1) & 0xFFFFFF00u) | km[2 * p]);
                r1 = min(r1, (hi32(e1) & 0xFFFFFF00u) | km[2 * p + 1]);
            }
            kw1 = __reduce_min_sync(0xffffffffu, min(r0, r1));
        }

        // Kill target1's winner.
        unsigned i1 = kw1 & 0xFFu;
        unsigned t1 = i1 - 8u * (unsigned)lane;
        #pragma unroll
        for (int s = 0; s < 8; s++)
            km[s] = (t1 == (unsigned)s) ? (km[s] | 0x80000000u) : km[s];

        // Uniform accumulate; index bits are denormal-magnitude noise and
        // 8-bit truncation bias ~2^-16 relative: both << 1e-3 tolerance.
        acc += __uint_as_float(kw0) + __uint_as_float(kw1);
    }

    // Sum of |t|^2 over the batch (warp butterfly, off critical path).
    #pragma unroll
    for (int off = 16; off; off >>= 1)
        tts += __shfl_xor_sync(0xffffffffu, tts, off);

    // se_j = d_j - 64 + |t_j|^2  =>  batch sum = acc + tts - 64*256
    if (lane == 0) g_partial[b] = acc + tts - 64.0f * NPTS;
    __threadfence();

    // Fused deterministic final reduction (last block, fixed order, fp64).
    int last = 0;
    if (lane == 0) last = (atomicAdd(&g_ctr, 1) == B_TOTAL - 1);
    last = __shfl_sync(0xffffffffu, last, 0);
    if (last) {
        __threadfence();
        double s = 0.0;
        #pragma unroll
        for (int i = 0; i < B_TOTAL / 32; i++)
            s += (double)g_partial[lane + 32 * i];
        #pragma unroll
        for (int off = 16; off; off >>= 1)
            s += __shfl_xor_sync(0xffffffffu, s, off);
        if (lane == 0) {
            out[0] = (float)(s / (double)B_TOTAL / (double)(2 * NPTS));
            g_ctr = 0;                  // reset for next graph replay
        }
    }
}

extern "C" void kernel_launch(void* const* d_in, const int* in_sizes, int n_in,
                              void* d_out, int out_size) {
    const float* inp = (const float*)d_in[0];   // "input"
    const float* tgt = (const float*)d_in[1];   // "targets"
    match_kernel<<<B_TOTAL, 32>>>(inp, tgt, (float*)d_out);
}